// round 2
// baseline (speedup 1.0000x reference)
#include <cuda_runtime.h>
#include <math.h>

#define T_ 100
#define B_ 64
#define I_ 256
#define H_ 512
#define G4_ (4*H_)   // 2048
#define H3_ (3*H_)   // 1536
#define BH_ (B_*H_)  // 32768

// ---------------- scratch (device globals; no allocation allowed) ----------
__device__ float g_xproj[(size_t)T_*B_*G4_];   // [T*B][4H] gates from input path (incl. biases)
__device__ float g_WhhT[(size_t)H_*G4_];       // [k=H][n=4H] transposed W_hh
__device__ float g_hseq[(size_t)(T_+1)*BH_];   // hseq[t] = h_{t-1}; hseq[0]=h_init
__device__ float g_cbuf[2*BH_];                // c double buffer
__device__ float g_f[(size_t)T_*BH_];          // forget gates per step
__device__ float g_d[(size_t)T_*B_*H3_];       // d_i|d_f|d_g per step; scaled in place by suffix products
__device__ float g_gpart[(size_t)16*B_*G4_];   // split-K partial sums for h@Whh^T

// ---------------- prep: transpose W_hh, copy initial state --------------------
__global__ void k_transpose(const float* __restrict__ Whh) {
    __shared__ float tile[32][33];
    int bx = blockIdx.x;            // k-tile (16)
    int by = blockIdx.y;            // n-tile (64)
    int tx = threadIdx.x, ty = threadIdx.y;   // 32 x 8
    int k = bx*32 + tx;
    #pragma unroll
    for (int i = 0; i < 32; i += 8) {
        int n = by*32 + ty + i;
        tile[ty+i][tx] = Whh[(size_t)n*H_ + k];
    }
    __syncthreads();
    int n2 = by*32 + tx;
    #pragma unroll
    for (int i = 0; i < 32; i += 8) {
        int k2 = bx*32 + ty + i;
        g_WhhT[(size_t)k2*G4_ + n2] = tile[tx][ty+i];
    }
}

__global__ void k_init(const float* __restrict__ h0, const float* __restrict__ c0) {
    int i = blockIdx.x*256 + threadIdx.x;
    if (i < BH_) { g_hseq[i] = h0[i]; g_cbuf[i] = c0[i]; }
}

// ---------------- K1: xproj = X @ Wih^T + b_ih + b_hh -------------------------
// M=T*B=6400, N=4H=2048, K=I=256.  128x128 tile, 8x8 per thread, lo/hi split.
__global__ __launch_bounds__(256, 2) void k1_xproj(
    const float* __restrict__ X, const float* __restrict__ W,
    const float* __restrict__ bih, const float* __restrict__ bhh)
{
    __shared__ float As[8][132];
    __shared__ float Ws[8][132];
    int m0 = blockIdx.y * 128;
    int n0 = blockIdx.x * 128;
    int tid = threadIdx.x;
    int lc = tid % 8;            // k within stage
    int lr = tid / 8;            // 32 rows per pass
    int ty = tid / 16, tx = tid % 16;

    float acc[8][8];
    #pragma unroll
    for (int i=0;i<8;i++)
        #pragma unroll
        for (int j=0;j<8;j++) acc[i][j]=0.f;

    for (int k0 = 0; k0 < I_; k0 += 8) {
        #pragma unroll
        for (int p = 0; p < 4; p++) {
            int r = lr + p*32;
            As[lc][r] = X[(size_t)(m0 + r)*I_ + k0 + lc];
            Ws[lc][r] = W[(size_t)(n0 + r)*I_ + k0 + lc];
        }
        __syncthreads();
        #pragma unroll
        for (int kk = 0; kk < 8; kk++) {
            float4 a0 = *(const float4*)&As[kk][ty*4];
            float4 a1 = *(const float4*)&As[kk][64 + ty*4];
            float4 b0 = *(const float4*)&Ws[kk][tx*4];
            float4 b1 = *(const float4*)&Ws[kk][64 + tx*4];
            float a[8] = {a0.x,a0.y,a0.z,a0.w,a1.x,a1.y,a1.z,a1.w};
            float bb[8]= {b0.x,b0.y,b0.z,b0.w,b1.x,b1.y,b1.z,b1.w};
            #pragma unroll
            for (int i=0;i<8;i++)
                #pragma unroll
                for (int j=0;j<8;j++) acc[i][j] += a[i]*bb[j];
        }
        __syncthreads();
    }
    float bias[8];
    #pragma unroll
    for (int j=0;j<8;j++) {
        int n = n0 + ((j<4)? tx*4 + j : 64 + tx*4 + (j-4));
        bias[j] = bih[n] + bhh[n];
    }
    #pragma unroll
    for (int i=0;i<8;i++) {
        int m = m0 + ((i<4)? ty*4+i : 64+ty*4+(i-4));
        float* row = g_xproj + (size_t)m*G4_ + n0;
        float4 v0 = make_float4(acc[i][0]+bias[0], acc[i][1]+bias[1],
                                acc[i][2]+bias[2], acc[i][3]+bias[3]);
        float4 v1 = make_float4(acc[i][4]+bias[4], acc[i][5]+bias[5],
                                acc[i][6]+bias[6], acc[i][7]+bias[7]);
        *(float4*)&row[tx*4]      = v0;
        *(float4*)&row[64+tx*4]   = v1;
    }
}

// ---------------- K2a: split-K GEMM gpart[kc] = h_{t-1} @ WhhT[kslice] --------
// grid (16 n-tiles of 128, 16 k-chunks of 32). Block 256 thr, thread = 4b x 8n.
__global__ __launch_bounds__(256, 2) void k2a_hw(int t)
{
    __shared__ float Hs[64][36];    // [b][k] (chunk of 32 k, pad to 36)
    __shared__ float Ws[32][128];   // [k][n]
    const float* hprev = g_hseq + (size_t)t*BH_;
    int n0 = blockIdx.x * 128;
    int kc = blockIdx.y;
    int k0 = kc * 32;
    int tid = threadIdx.x;

    {   // load h: 64 x 32
        int kcol = (tid & 7) * 4, brow = tid >> 3;   // 32 rows/pass
        #pragma unroll
        for (int p=0;p<2;p++) {
            int b = brow + p*32;
            float4 v = *(const float4*)&hprev[(size_t)b*H_ + k0 + kcol];
            *(float4*)&Hs[b][kcol] = v;
        }
    }
    {   // load W: 32 x 128
        int ncol = (tid & 31) * 4, krow = tid >> 5;  // 8 rows/pass
        #pragma unroll
        for (int p=0;p<4;p++) {
            int k = krow + p*8;
            float4 v = *(const float4*)&g_WhhT[(size_t)(k0+k)*G4_ + n0 + ncol];
            *(float4*)&Ws[k][ncol] = v;
        }
    }
    __syncthreads();

    int bg = tid >> 4, ng = tid & 15;
    int b0 = bg*4;
    float acc[4][8];
    #pragma unroll
    for (int i=0;i<4;i++)
        #pragma unroll
        for (int j=0;j<8;j++) acc[i][j]=0.f;

    #pragma unroll 4
    for (int k=0;k<32;k++) {
        float4 w0 = *(const float4*)&Ws[k][ng*4];
        float4 w1 = *(const float4*)&Ws[k][64+ng*4];
        float w[8] = {w0.x,w0.y,w0.z,w0.w,w1.x,w1.y,w1.z,w1.w};
        #pragma unroll
        for (int i=0;i<4;i++) {
            float hv = Hs[b0+i][k];
            #pragma unroll
            for (int j=0;j<8;j++) acc[i][j] += hv*w[j];
        }
    }
    #pragma unroll
    for (int i=0;i<4;i++) {
        float* row = g_gpart + ((size_t)kc*B_ + b0 + i)*G4_ + n0;
        *(float4*)&row[ng*4]    = make_float4(acc[i][0],acc[i][1],acc[i][2],acc[i][3]);
        *(float4*)&row[64+ng*4] = make_float4(acc[i][4],acc[i][5],acc[i][6],acc[i][7]);
    }
}

// ---------------- K2b: reduce partials + LSTM pointwise + e-prop derivs ------
__global__ void k2b_point(int t, float* __restrict__ out_h, float* __restrict__ out_cx)
{
    int idx = blockIdx.x*256 + threadIdx.x;   // < BH_
    int b = idx >> 9;
    int h = idx & 511;
    const float* xp = g_xproj + ((size_t)t*B_ + b)*G4_;
    float ai = xp[h], af = xp[H_+h], ag = xp[2*H_+h], ao = xp[3*H_+h];
    #pragma unroll
    for (int kc=0;kc<16;kc++) {
        const float* gp = g_gpart + ((size_t)kc*B_ + b)*G4_;
        ai += gp[h]; af += gp[H_+h]; ag += gp[2*H_+h]; ao += gp[3*H_+h];
    }
    float ig = 1.f/(1.f+expf(-ai));
    float fg = 1.f/(1.f+expf(-af));
    float gg = tanhf(ag);
    float og = 1.f/(1.f+expf(-ao));
    float cprev = g_cbuf[(t&1)*BH_ + idx];
    float cy = fg*cprev + ig*gg;
    float hy = og*tanhf(cy);
    g_cbuf[((t+1)&1)*BH_ + idx] = cy;
    out_h[(size_t)t*BH_ + idx] = hy;
    g_hseq[(size_t)(t+1)*BH_ + idx] = hy;
    g_f[(size_t)t*BH_ + idx] = fg;
    float* dp = g_d + ((size_t)t*B_ + b)*H3_;
    dp[h]        = gg*ig*(1.f-ig);
    dp[H_+h]     = cprev*fg*(1.f-fg);
    dp[2*H_+h]   = ig*(1.f-gg*gg);
    if (t == T_-1) out_cx[idx] = cy;
}

// ---------------- K3: suffix forget-product scan; scales d in place; ev_b ----
__global__ void k3_suffix(float* __restrict__ out_evb)
{
    int idx = blockIdx.x*256 + threadIdx.x;   // < BH_
    int b = idx >> 9;
    int h = idx & 511;
    float p = 1.f, s0 = 0.f, s1 = 0.f, s2 = 0.f;
    for (int t = T_-1; t >= 0; --t) {
        float* dp = g_d + ((size_t)t*B_ + b)*H3_;
        float di = dp[h]*p, df = dp[H_+h]*p, dg = dp[2*H_+h]*p;
        dp[h] = di; dp[H_+h] = df; dp[2*H_+h] = dg;
        s0 += di; s1 += df; s2 += dg;
        p *= g_f[(size_t)t*BH_ + idx];
    }
    out_evb[(size_t)b*H3_ + h]        = s0;
    out_evb[(size_t)b*H3_ + H_ + h]   = s1;
    out_evb[(size_t)b*H3_ + 2*H_ + h] = s2;
}

// ---------------- K4/K5: batched ev GEMM  C[b] = A[b]^T (3H x T) @ X[b] (T x Idim)
// A = g_d (already suffix-scaled). X = input (Idim=I) or g_hseq (Idim=H, X=null).
__global__ __launch_bounds__(256, 2) void k_ev(
    const float* __restrict__ Xin, float* __restrict__ C, int Idim)
{
    __shared__ float As[8][132];
    __shared__ float Xs[8][132];
    const float* X = Xin ? Xin : (const float*)g_hseq;  // hseq[t] = h_{t-1}
    int i0 = blockIdx.x*128;
    int j0 = blockIdx.y*128;
    int b  = blockIdx.z;
    int tid = threadIdx.x;
    int ty = tid/16, tx = tid%16;
    int lk = tid >> 5;            // 0..7
    int lj = (tid & 31) * 4;      // 0..124

    float acc[8][8];
    #pragma unroll
    for (int i=0;i<8;i++)
        #pragma unroll
        for (int j=0;j<8;j++) acc[i][j]=0.f;

    for (int t0 = 0; t0 < T_; t0 += 8) {
        int t = t0 + lk;
        if (t < T_) {
            *(float4*)&As[lk][lj] = *(const float4*)&g_d[((size_t)t*B_+b)*H3_ + j0 + lj];
            *(float4*)&Xs[lk][lj] = *(const float4*)&X[((size_t)t*B_+b)*Idim + i0 + lj];
        } else {
            float4 z = make_float4(0.f,0.f,0.f,0.f);
            *(float4*)&As[lk][lj] = z;
            *(float4*)&Xs[lk][lj] = z;
        }
        __syncthreads();
        #pragma unroll
        for (int kk=0;kk<8;kk++) {
            float4 a0 = *(const float4*)&As[kk][ty*4];
            float4 a1 = *(const float4*)&As[kk][64+ty*4];
            float4 x0 = *(const float4*)&Xs[kk][tx*4];
            float4 x1 = *(const float4*)&Xs[kk][64+tx*4];
            float a[8] = {a0.x,a0.y,a0.z,a0.w,a1.x,a1.y,a1.z,a1.w};
            float x[8] = {x0.x,x0.y,x0.z,x0.w,x1.x,x1.y,x1.z,x1.w};
            #pragma unroll
            for (int i=0;i<8;i++)
                #pragma unroll
                for (int j=0;j<8;j++) acc[i][j] += a[i]*x[j];
        }
        __syncthreads();
    }
    #pragma unroll
    for (int i=0;i<8;i++) {
        int j = j0 + ((i<4)? ty*4+i : 64+ty*4+(i-4));
        float* row = C + (size_t)b*H3_*Idim + (size_t)j*Idim + i0;
        *(float4*)&row[tx*4]    = make_float4(acc[i][0],acc[i][1],acc[i][2],acc[i][3]);
        *(float4*)&row[64+tx*4] = make_float4(acc[i][4],acc[i][5],acc[i][6],acc[i][7]);
    }
}

// ---------------- launch --------------------------------------------------------
extern "C" void kernel_launch(void* const* d_in, const int* in_sizes, int n_in,
                              void* d_out, int out_size)
{
    const float* input = (const float*)d_in[0];   // [T,B,I]
    const float* h0    = (const float*)d_in[1];   // [B,H]
    const float* c0    = (const float*)d_in[2];   // [B,H]
    const float* Wih   = (const float*)d_in[3];   // [4H,I]
    const float* Whh   = (const float*)d_in[4];   // [4H,H]
    const float* bih   = (const float*)d_in[5];   // [4H]
    const float* bhh   = (const float*)d_in[6];   // [4H]

    float* out      = (float*)d_out;
    float* out_h    = out;                                    // [T,B,H]
    float* out_cx   = out_h  + (size_t)T_*BH_;                // [B,H]
    float* out_evih = out_cx + BH_;                           // [B,3H,I]
    float* out_evhh = out_evih + (size_t)B_*H3_*I_;           // [B,3H,H]
    float* out_evb  = out_evhh + (size_t)B_*H3_*H_;           // [B,3H]

    k_transpose<<<dim3(16,64), dim3(32,8)>>>(Whh);
    k_init<<<128,256>>>(h0, c0);
    k1_xproj<<<dim3(16,50),256>>>(input, Wih, bih, bhh);

    for (int t = 0; t < T_; ++t) {
        k2a_hw<<<dim3(16,16),256>>>(t);
        k2b_point<<<128,256>>>(t, out_h, out_cx);
    }

    k3_suffix<<<128,256>>>(out_evb);

    k_ev<<<dim3(I_/128, H3_/128, B_),256>>>(input, out_evih, I_);
    k_ev<<<dim3(H_/128, H3_/128, B_),256>>>(nullptr, out_evhh, H_);
}

// round 3
// speedup vs baseline: 1.0017x; 1.0017x over previous
#include <cuda_runtime.h>
#include <math.h>

#define T_ 100
#define B_ 64
#define I_ 256
#define H_ 512
#define G4_ (4*H_)   // 2048
#define H3_ (3*H_)   // 1536
#define BH_ (B_*H_)  // 32768

// ---------------- scratch (device globals; no allocation allowed) ----------
__device__ float g_xproj[(size_t)T_*B_*G4_];   // [T*B][4H] gates from input path (incl. biases)
__device__ float g_WhhT[(size_t)H_*G4_];       // [k=H][n=4H] transposed W_hh
__device__ float g_hseq[(size_t)(T_+1)*BH_];   // hseq[t] = h_{t-1}; hseq[0]=h_init
__device__ float g_cbuf[2*BH_];                // c double buffer
__device__ float g_f[(size_t)T_*BH_];          // forget gates per step
__device__ float g_d[(size_t)T_*B_*H3_];       // d_i|d_f|d_g per step; scaled in place by suffix products
__device__ float g_gpart[(size_t)16*B_*G4_];   // split-K partial sums for h@Whh^T

// ---------------- prep: transpose W_hh, copy initial state --------------------
__global__ void k_transpose(const float* __restrict__ Whh) {
    __shared__ float tile[32][33];
    int bx = blockIdx.x;            // k-tile (16)
    int by = blockIdx.y;            // n-tile (64)
    int tx = threadIdx.x, ty = threadIdx.y;   // 32 x 8
    int k = bx*32 + tx;
    #pragma unroll
    for (int i = 0; i < 32; i += 8) {
        int n = by*32 + ty + i;
        tile[ty+i][tx] = Whh[(size_t)n*H_ + k];
    }
    __syncthreads();
    int n2 = by*32 + tx;
    #pragma unroll
    for (int i = 0; i < 32; i += 8) {
        int k2 = bx*32 + ty + i;
        g_WhhT[(size_t)k2*G4_ + n2] = tile[tx][ty+i];
    }
}

__global__ void k_init(const float* __restrict__ h0, const float* __restrict__ c0) {
    int i = blockIdx.x*256 + threadIdx.x;
    if (i < BH_) { g_hseq[i] = h0[i]; g_cbuf[i] = c0[i]; }
}

// ---------------- K1: xproj = X @ Wih^T + b_ih + b_hh -------------------------
// M=T*B=6400, N=4H=2048, K=I=256.  128x128 tile, 8x8 per thread, lo/hi split.
__global__ __launch_bounds__(256, 2) void k1_xproj(
    const float* __restrict__ X, const float* __restrict__ W,
    const float* __restrict__ bih, const float* __restrict__ bhh)
{
    __shared__ float As[8][132];
    __shared__ float Ws[8][132];
    int m0 = blockIdx.y * 128;
    int n0 = blockIdx.x * 128;
    int tid = threadIdx.x;
    int lc = tid % 8;            // k within stage
    int lr = tid / 8;            // 32 rows per pass
    int ty = tid / 16, tx = tid % 16;

    float acc[8][8];
    #pragma unroll
    for (int i=0;i<8;i++)
        #pragma unroll
        for (int j=0;j<8;j++) acc[i][j]=0.f;

    for (int k0 = 0; k0 < I_; k0 += 8) {
        #pragma unroll
        for (int p = 0; p < 4; p++) {
            int r = lr + p*32;
            As[lc][r] = X[(size_t)(m0 + r)*I_ + k0 + lc];
            Ws[lc][r] = W[(size_t)(n0 + r)*I_ + k0 + lc];
        }
        __syncthreads();
        #pragma unroll
        for (int kk = 0; kk < 8; kk++) {
            float4 a0 = *(const float4*)&As[kk][ty*4];
            float4 a1 = *(const float4*)&As[kk][64 + ty*4];
            float4 b0 = *(const float4*)&Ws[kk][tx*4];
            float4 b1 = *(const float4*)&Ws[kk][64 + tx*4];
            float a[8] = {a0.x,a0.y,a0.z,a0.w,a1.x,a1.y,a1.z,a1.w};
            float bb[8]= {b0.x,b0.y,b0.z,b0.w,b1.x,b1.y,b1.z,b1.w};
            #pragma unroll
            for (int i=0;i<8;i++)
                #pragma unroll
                for (int j=0;j<8;j++) acc[i][j] += a[i]*bb[j];
        }
        __syncthreads();
    }
    float bias[8];
    #pragma unroll
    for (int j=0;j<8;j++) {
        int n = n0 + ((j<4)? tx*4 + j : 64 + tx*4 + (j-4));
        bias[j] = bih[n] + bhh[n];
    }
    #pragma unroll
    for (int i=0;i<8;i++) {
        int m = m0 + ((i<4)? ty*4+i : 64+ty*4+(i-4));
        float* row = g_xproj + (size_t)m*G4_ + n0;
        float4 v0 = make_float4(acc[i][0]+bias[0], acc[i][1]+bias[1],
                                acc[i][2]+bias[2], acc[i][3]+bias[3]);
        float4 v1 = make_float4(acc[i][4]+bias[4], acc[i][5]+bias[5],
                                acc[i][6]+bias[6], acc[i][7]+bias[7]);
        *(float4*)&row[tx*4]      = v0;
        *(float4*)&row[64+tx*4]   = v1;
    }
}

// ---------------- K2a: split-K GEMM gpart[kc] = h_{t-1} @ WhhT[kslice] --------
// grid (16 n-tiles of 128, 16 k-chunks of 32). Block 256 thr, thread = 4b x 8n.
__global__ __launch_bounds__(256, 2) void k2a_hw(int t)
{
    __shared__ float Hs[64][36];    // [b][k] (chunk of 32 k, pad to 36)
    __shared__ float Ws[32][128];   // [k][n]
    const float* hprev = g_hseq + (size_t)t*BH_;
    int n0 = blockIdx.x * 128;
    int kc = blockIdx.y;
    int k0 = kc * 32;
    int tid = threadIdx.x;

    {   // load h: 64 x 32
        int kcol = (tid & 7) * 4, brow = tid >> 3;   // 32 rows/pass
        #pragma unroll
        for (int p=0;p<2;p++) {
            int b = brow + p*32;
            float4 v = *(const float4*)&hprev[(size_t)b*H_ + k0 + kcol];
            *(float4*)&Hs[b][kcol] = v;
        }
    }
    {   // load W: 32 x 128
        int ncol = (tid & 31) * 4, krow = tid >> 5;  // 8 rows/pass
        #pragma unroll
        for (int p=0;p<4;p++) {
            int k = krow + p*8;
            float4 v = *(const float4*)&g_WhhT[(size_t)(k0+k)*G4_ + n0 + ncol];
            *(float4*)&Ws[k][ncol] = v;
        }
    }
    __syncthreads();

    int bg = tid >> 4, ng = tid & 15;
    int b0 = bg*4;
    float acc[4][8];
    #pragma unroll
    for (int i=0;i<4;i++)
        #pragma unroll
        for (int j=0;j<8;j++) acc[i][j]=0.f;

    #pragma unroll 4
    for (int k=0;k<32;k++) {
        float4 w0 = *(const float4*)&Ws[k][ng*4];
        float4 w1 = *(const float4*)&Ws[k][64+ng*4];
        float w[8] = {w0.x,w0.y,w0.z,w0.w,w1.x,w1.y,w1.z,w1.w};
        #pragma unroll
        for (int i=0;i<4;i++) {
            float hv = Hs[b0+i][k];
            #pragma unroll
            for (int j=0;j<8;j++) acc[i][j] += hv*w[j];
        }
    }
    #pragma unroll
    for (int i=0;i<4;i++) {
        float* row = g_gpart + ((size_t)kc*B_ + b0 + i)*G4_ + n0;
        *(float4*)&row[ng*4]    = make_float4(acc[i][0],acc[i][1],acc[i][2],acc[i][3]);
        *(float4*)&row[64+ng*4] = make_float4(acc[i][4],acc[i][5],acc[i][6],acc[i][7]);
    }
}

// ---------------- K2b: reduce partials + LSTM pointwise + e-prop derivs ------
__global__ void k2b_point(int t, float* __restrict__ out_h, float* __restrict__ out_cx)
{
    int idx = blockIdx.x*256 + threadIdx.x;   // < BH_
    int b = idx >> 9;
    int h = idx & 511;
    const float* xp = g_xproj + ((size_t)t*B_ + b)*G4_;
    float ai = xp[h], af = xp[H_+h], ag = xp[2*H_+h], ao = xp[3*H_+h];
    #pragma unroll
    for (int kc=0;kc<16;kc++) {
        const float* gp = g_gpart + ((size_t)kc*B_ + b)*G4_;
        ai += gp[h]; af += gp[H_+h]; ag += gp[2*H_+h]; ao += gp[3*H_+h];
    }
    float ig = 1.f/(1.f+expf(-ai));
    float fg = 1.f/(1.f+expf(-af));
    float gg = tanhf(ag);
    float og = 1.f/(1.f+expf(-ao));
    float cprev = g_cbuf[(t&1)*BH_ + idx];
    float cy = fg*cprev + ig*gg;
    float hy = og*tanhf(cy);
    g_cbuf[((t+1)&1)*BH_ + idx] = cy;
    out_h[(size_t)t*BH_ + idx] = hy;
    g_hseq[(size_t)(t+1)*BH_ + idx] = hy;
    g_f[(size_t)t*BH_ + idx] = fg;
    float* dp = g_d + ((size_t)t*B_ + b)*H3_;
    dp[h]        = gg*ig*(1.f-ig);
    dp[H_+h]     = cprev*fg*(1.f-fg);
    dp[2*H_+h]   = ig*(1.f-gg*gg);
    if (t == T_-1) out_cx[idx] = cy;
}

// ---------------- K3: suffix forget-product scan; scales d in place; ev_b ----
__global__ void k3_suffix(float* __restrict__ out_evb)
{
    int idx = blockIdx.x*256 + threadIdx.x;   // < BH_
    int b = idx >> 9;
    int h = idx & 511;
    float p = 1.f, s0 = 0.f, s1 = 0.f, s2 = 0.f;
    for (int t = T_-1; t >= 0; --t) {
        float* dp = g_d + ((size_t)t*B_ + b)*H3_;
        float di = dp[h]*p, df = dp[H_+h]*p, dg = dp[2*H_+h]*p;
        dp[h] = di; dp[H_+h] = df; dp[2*H_+h] = dg;
        s0 += di; s1 += df; s2 += dg;
        p *= g_f[(size_t)t*BH_ + idx];
    }
    out_evb[(size_t)b*H3_ + h]        = s0;
    out_evb[(size_t)b*H3_ + H_ + h]   = s1;
    out_evb[(size_t)b*H3_ + 2*H_ + h] = s2;
}

// ---------------- K4/K5: batched ev GEMM  C[b] = A[b]^T (3H x T) @ X[b] (T x Idim)
// A = g_d (already suffix-scaled). X = input (Idim=I) or g_hseq (Idim=H, X=null).
__global__ __launch_bounds__(256, 2) void k_ev(
    const float* __restrict__ Xin, float* __restrict__ C, int Idim)
{
    __shared__ float As[8][132];
    __shared__ float Xs[8][132];
    const float* X = Xin ? Xin : (const float*)g_hseq;  // hseq[t] = h_{t-1}
    int i0 = blockIdx.x*128;
    int j0 = blockIdx.y*128;
    int b  = blockIdx.z;
    int tid = threadIdx.x;
    int ty = tid/16, tx = tid%16;
    int lk = tid >> 5;            // 0..7
    int lj = (tid & 31) * 4;      // 0..124

    float acc[8][8];
    #pragma unroll
    for (int i=0;i<8;i++)
        #pragma unroll
        for (int j=0;j<8;j++) acc[i][j]=0.f;

    for (int t0 = 0; t0 < T_; t0 += 8) {
        int t = t0 + lk;
        if (t < T_) {
            *(float4*)&As[lk][lj] = *(const float4*)&g_d[((size_t)t*B_+b)*H3_ + j0 + lj];
            *(float4*)&Xs[lk][lj] = *(const float4*)&X[((size_t)t*B_+b)*Idim + i0 + lj];
        } else {
            float4 z = make_float4(0.f,0.f,0.f,0.f);
            *(float4*)&As[lk][lj] = z;
            *(float4*)&Xs[lk][lj] = z;
        }
        __syncthreads();
        #pragma unroll
        for (int kk=0;kk<8;kk++) {
            float4 a0 = *(const float4*)&As[kk][ty*4];
            float4 a1 = *(const float4*)&As[kk][64+ty*4];
            float4 x0 = *(const float4*)&Xs[kk][tx*4];
            float4 x1 = *(const float4*)&Xs[kk][64+tx*4];
            float a[8] = {a0.x,a0.y,a0.z,a0.w,a1.x,a1.y,a1.z,a1.w};
            float x[8] = {x0.x,x0.y,x0.z,x0.w,x1.x,x1.y,x1.z,x1.w};
            #pragma unroll
            for (int i=0;i<8;i++)
                #pragma unroll
                for (int j=0;j<8;j++) acc[i][j] += a[i]*x[j];
        }
        __syncthreads();
    }
    #pragma unroll
    for (int i=0;i<8;i++) {
        int j = j0 + ((i<4)? ty*4+i : 64+ty*4+(i-4));
        float* row = C + (size_t)b*H3_*Idim + (size_t)j*Idim + i0;
        *(float4*)&row[tx*4]    = make_float4(acc[i][0],acc[i][1],acc[i][2],acc[i][3]);
        *(float4*)&row[64+tx*4] = make_float4(acc[i][4],acc[i][5],acc[i][6],acc[i][7]);
    }
}

// ---------------- launch --------------------------------------------------------
extern "C" void kernel_launch(void* const* d_in, const int* in_sizes, int n_in,
                              void* d_out, int out_size)
{
    const float* input = (const float*)d_in[0];   // [T,B,I]
    const float* h0    = (const float*)d_in[1];   // [B,H]
    const float* c0    = (const float*)d_in[2];   // [B,H]
    const float* Wih   = (const float*)d_in[3];   // [4H,I]
    const float* Whh   = (const float*)d_in[4];   // [4H,H]
    const float* bih   = (const float*)d_in[5];   // [4H]
    const float* bhh   = (const float*)d_in[6];   // [4H]

    float* out      = (float*)d_out;
    float* out_h    = out;                                    // [T,B,H]
    float* out_cx   = out_h  + (size_t)T_*BH_;                // [B,H]
    float* out_evih = out_cx + BH_;                           // [B,3H,I]
    float* out_evhh = out_evih + (size_t)B_*H3_*I_;           // [B,3H,H]
    float* out_evb  = out_evhh + (size_t)B_*H3_*H_;           // [B,3H]

    k_transpose<<<dim3(16,64), dim3(32,8)>>>(Whh);
    k_init<<<128,256>>>(h0, c0);
    k1_xproj<<<dim3(16,50),256>>>(input, Wih, bih, bhh);

    for (int t = 0; t < T_; ++t) {
        k2a_hw<<<dim3(16,16),256>>>(t);
        k2b_point<<<128,256>>>(t, out_h, out_cx);
    }

    k3_suffix<<<128,256>>>(out_evb);

    k_ev<<<dim3(I_/128, H3_/128, B_),256>>>(input, out_evih, I_);
    k_ev<<<dim3(H_/128, H3_/128, B_),256>>>(nullptr, out_evhh, H_);
}